// round 9
// baseline (speedup 1.0000x reference)
#include <cuda_runtime.h>
#include <cuda_bf16.h>
#include <math.h>
#include <stdint.h>

#define Nn   50000
#define Ee   800000
#define HIDc 128
#define MLPc 512
#define MODSc 768

// packed weight split buffer offsets (in uints; kp-major, [K/2][N])
#define W_ADA_OFF   0            // 64*768 = 49152
#define W_QKV_OFF   49152        // 64*384 = 24576
#define W_PROJ_OFF  73728        // 64*128 = 8192
#define W_MLP1_OFF  81920        // 64*512 = 32768
#define W_MLP2_OFF  114688       // 256*128 = 32768
#define W_TOTAL     147456

// ---------------- scratch (device globals; no allocation allowed) ----------
__device__ float g_mods[Nn * MODSc];
__device__ float g_xmod[Nn * HIDc];
__device__ float g_qkv [Nn * 3 * HIDc];
__device__ float g_score[(size_t)Ee * 8];
__device__ float g_smax[Nn * 8];
__device__ float g_den [Nn * 8];
__device__ float g_agg [Nn * HIDc];
__device__ float g_x1  [Nn * HIDc];
__device__ float g_h1  [Nn * MLPc];
__device__ int   g_src [Ee];
__device__ int   g_dst [Ee];
__device__ int   g_is64;
__device__ unsigned g_whi[W_TOTAL];
__device__ unsigned g_wlo[W_TOTAL];

// ---------------- helpers ---------------------------------------------------
__device__ __forceinline__ uint32_t smem_u32(const void* p) {
    uint32_t a;
    asm("{ .reg .u64 t; cvta.to.shared.u64 t, %1; cvt.u32.u64 %0, t; }" : "=r"(a) : "l"(p));
    return a;
}

__device__ __forceinline__ void cpasync16(uint32_t s, const void* g) {
    asm volatile("cp.async.ca.shared.global [%0], [%1], 16;" :: "r"(s), "l"(g));
}
#define CP_COMMIT() asm volatile("cp.async.commit_group;" ::: "memory")
#define CP_WAIT0()  asm volatile("cp.async.wait_group 0;" ::: "memory")

__device__ __forceinline__ void atomicMaxFloat(float* addr, float value) {
    if (value >= 0.0f)
        atomicMax((int*)addr, __float_as_int(value));
    else
        atomicMin((unsigned int*)addr, __float_as_uint(value));
}

__device__ __forceinline__ void redAdd4(float* addr, float4 v) {
    asm volatile("red.global.add.v4.f32 [%0], {%1, %2, %3, %4};"
                 :: "l"(addr), "f"(v.x), "f"(v.y), "f"(v.z), "f"(v.w)
                 : "memory");
}

// split a float pair into packed bf16x2 hi and lo
__device__ __forceinline__ void bf16_split2(float e, float o, unsigned& hi, unsigned& lo) {
    __nv_bfloat162 h2 = __floats2bfloat162_rn(e, o);
    float he = __bfloat162float(h2.x);
    float ho = __bfloat162float(h2.y);
    __nv_bfloat162 l2 = __floats2bfloat162_rn(e - he, o - ho);
    hi = *(unsigned*)&h2;
    lo = *(unsigned*)&l2;
}

__device__ __forceinline__ void mma16(float* c, const unsigned* a, const unsigned* b) {
    asm volatile("mma.sync.aligned.m16n8k16.row.col.f32.bf16.bf16.f32 "
                 "{%0,%1,%2,%3}, {%4,%5,%6,%7}, {%8,%9}, {%0,%1,%2,%3};"
                 : "+f"(c[0]), "+f"(c[1]), "+f"(c[2]), "+f"(c[3])
                 : "r"(a[0]), "r"(a[1]), "r"(a[2]), "r"(a[3]),
                   "r"(b[0]), "r"(b[1]));
}

// ---------------- weight pre-split ------------------------------------------
__global__ void k_wsplit(const float* __restrict__ W, int Kd, int N,
                         unsigned* __restrict__ hi, unsigned* __restrict__ lo) {
    int t = blockIdx.x * blockDim.x + threadIdx.x;
    int total = (Kd / 2) * N;
    if (t >= total) return;
    int kp = t / N, n = t - kp * N;
    float e = W[(size_t)(2 * kp) * N + n];
    float o = W[(size_t)(2 * kp + 1) * N + n];
    unsigned h, l;
    bf16_split2(e, o, h, l);
    hi[t] = h; lo[t] = l;
}

// ---------------- edge-index dtype probe + conversion ------------------------
__global__ void k_flag_init() { g_is64 = 1; }

__global__ void k_detect(const void* __restrict__ ei) {
    int t = blockIdx.x * blockDim.x + threadIdx.x;
    if (t >= Ee) return;
    long long v = ((const long long*)ei)[t];
    if (v < 0 || v >= (long long)Nn) g_is64 = 0;
}

__global__ void k_convert(const void* __restrict__ ei) {
    int t = blockIdx.x * blockDim.x + threadIdx.x;
    if (t >= Ee) return;
    if (g_is64) {
        g_src[t] = (int)((const long long*)ei)[t];
        g_dst[t] = (int)((const long long*)ei)[Ee + t];
    } else {
        g_src[t] = ((const int*)ei)[t];
        g_dst[t] = ((const int*)ei)[Ee + t];
    }
}

// ---------------- elementwise kernels ---------------------------------------
__global__ void k_init() {
    int t = blockIdx.x * blockDim.x + threadIdx.x;
    if (t < Nn * HIDc) g_agg[t] = 0.0f;
    if (t < Nn * 8) { g_den[t] = 0.0f; g_smax[t] = -INFINITY; }
}

__global__ void k_ln_mod(const float* __restrict__ x, const float* __restrict__ mods,
                         int shift_off, int scale_off, float* __restrict__ out) {
    int warp = (blockIdx.x * blockDim.x + threadIdx.x) >> 5;
    int lane = threadIdx.x & 31;
    if (warp >= Nn) return;
    const float4 xv = *(const float4*)&x[(size_t)warp * HIDc + lane * 4];
    float s  = xv.x + xv.y + xv.z + xv.w;
    float s2 = xv.x*xv.x + xv.y*xv.y + xv.z*xv.z + xv.w*xv.w;
    #pragma unroll
    for (int o = 16; o; o >>= 1) {
        s  += __shfl_xor_sync(0xffffffffu, s,  o);
        s2 += __shfl_xor_sync(0xffffffffu, s2, o);
    }
    float mean = s * (1.0f / 128.0f);
    float var  = s2 * (1.0f / 128.0f) - mean * mean;
    float rstd = rsqrtf(var + 1e-6f);
    const float4 sh = *(const float4*)&mods[(size_t)warp * MODSc + shift_off + lane * 4];
    const float4 sc = *(const float4*)&mods[(size_t)warp * MODSc + scale_off + lane * 4];
    float4 o4;
    o4.x = (xv.x - mean) * rstd * (1.0f + sc.x) + sh.x;
    o4.y = (xv.y - mean) * rstd * (1.0f + sc.y) + sh.y;
    o4.z = (xv.z - mean) * rstd * (1.0f + sc.z) + sh.z;
    o4.w = (xv.w - mean) * rstd * (1.0f + sc.w) + sh.w;
    *(float4*)&out[(size_t)warp * HIDc + lane * 4] = o4;
}

// ---------------- edge kernels ----------------------------------------------
__global__ void k_edge_score(const float* __restrict__ qkv) {
    long long t = (long long)blockIdx.x * blockDim.x + threadIdx.x;
    if (t >= (long long)Ee * 8) return;
    int e = (int)(t >> 3);
    int h = (int)(t & 7);
    int src = g_src[e];
    int dst = g_dst[e];
    const float* q = &qkv[(size_t)dst * 384 + h * 16];
    const float* k = &qkv[(size_t)src * 384 + 128 + h * 16];
    float d = 0.0f;
    #pragma unroll
    for (int i = 0; i < 4; i++) {
        float4 qv = *(const float4*)&q[i * 4];
        float4 kv = *(const float4*)&k[i * 4];
        d += qv.x*kv.x + qv.y*kv.y + qv.z*kv.z + qv.w*kv.w;
    }
    d *= 0.25f;
    g_score[t] = d;
    atomicMaxFloat(&g_smax[dst * 8 + h], d);
}

__global__ void k_edge_msg(const float* __restrict__ qkv) {
    long long t = (long long)blockIdx.x * blockDim.x + threadIdx.x;
    if (t >= (long long)Ee * 8) return;
    int e = (int)(t >> 3);
    int h = (int)(t & 7);
    int src = g_src[e];
    int dst = g_dst[e];
    float sc = g_score[t];
    float ex = expf(sc - g_smax[dst * 8 + h]);
    atomicAdd(&g_den[dst * 8 + h], ex);
    const float* v = &qkv[(size_t)src * 384 + 256 + h * 16];
    float* a = &g_agg[(size_t)dst * HIDc + h * 16];
    #pragma unroll
    for (int i = 0; i < 4; i++) {
        float4 vv = *(const float4*)&v[i * 4];
        redAdd4(&a[i * 4], make_float4(vv.x * ex, vv.y * ex, vv.z * ex, vv.w * ex));
    }
}

__global__ void k_norm() {
    int t = blockIdx.x * blockDim.x + threadIdx.x;
    if (t >= Nn * 32) return;
    int n = t >> 5;
    int h = (t >> 2) & 7;
    float dd = g_den[n * 8 + h];
    float inv = (dd > 0.0f) ? (1.0f / dd) : 0.0f;
    float4 v = *(float4*)&g_agg[t * 4];
    v.x *= inv; v.y *= inv; v.z *= inv; v.w *= inv;
    *(float4*)&g_agg[t * 4] = v;
}

// ---------------- 3xBF16 tensor-core GEMM (BK=32, double-buffered) ----------
// C[M,N] = epi(A[M,K] @ B[K,N] + bias), B given as packed bf16x2 hi/lo [K/2][N]
// 128x128 block tile, BK=32 (16 kp rows), 256 threads, 8 warps (2x4 warp grid,
// 64x32 warp tile), mma.m16n8k16.bf16, 3 split terms (hh, hl, lh).
// Two smem stages; B via cp.async, A staged 2 chunks ahead in registers.
// PRE 0: raw A   PRE 1: silu(A)
// EPI 0: +bias   EPI 1: gelu(tanh)   EPI 2: resid + gate*(acc+bias)
#define PADg   136
#define ARR_B  (16 * PADg * 4)       // 8704 bytes per array
#define STAGE  (4 * ARR_B)           // 34816 bytes per stage
#define SMTOT  (2 * STAGE)           // 69632

template<int EPI, int PRE>
__global__ __launch_bounds__(256)
void bgemm128(const float* __restrict__ A,
              const unsigned* __restrict__ Bhi, const unsigned* __restrict__ Blo,
              const float* __restrict__ bias, float* __restrict__ C,
              int M, int N, int K,
              const float* __restrict__ resid,
              const float* __restrict__ gate, int gate_stride) {
    extern __shared__ char smem[];

    const int tid = threadIdx.x;
    const int warpId = tid >> 5;
    const int lane = tid & 31;
    const int gr = lane >> 2;
    const int tg = lane & 3;
    const int warpRow = warpId >> 2;
    const int warpCol = warpId & 3;
    const int rowBase = blockIdx.y * 128;
    const int colBase = blockIdx.x * 128;

    // A fill map: row + 16-float k-half
    const int ar = tid & 127;
    const int ah2 = tid >> 7;             // 0/1
    const bool aok = (rowBase + ar) < M;
    const float* aRow = A + (size_t)(rowBase + ar) * K + ah2 * 16;
    // B fill map: kp row + 8-uint n group
    const int bkp = tid >> 4;             // 0..15
    const int bn0 = (tid & 15) * 8;       // 0..120
    const unsigned* bhRow = Bhi + (size_t)bkp * N + colBase + bn0;
    const unsigned* blRow = Blo + (size_t)bkp * N + colBase + bn0;

    float acc[4][4][4];
    #pragma unroll
    for (int i = 0; i < 4; i++)
        #pragma unroll
        for (int j = 0; j < 4; j++)
            #pragma unroll
            for (int r = 0; r < 4; r++) acc[i][j][r] = 0.0f;

    float4 aS[4];

    auto ldgA = [&](int c) {
        if (aok) {
            const float* p = aRow + c * 32;
            aS[0] = *(const float4*)p;
            aS[1] = *(const float4*)(p + 4);
            aS[2] = *(const float4*)(p + 8);
            aS[3] = *(const float4*)(p + 12);
        } else {
            aS[0] = aS[1] = aS[2] = aS[3] = make_float4(0.f, 0.f, 0.f, 0.f);
        }
    };
    auto stsA = [&](int c) {
        char* st = smem + (c & 1) * STAGE;
        unsigned (*Ah)[PADg] = (unsigned(*)[PADg])st;
        unsigned (*Al)[PADg] = (unsigned(*)[PADg])(st + ARR_B);
        float vv[16] = {aS[0].x, aS[0].y, aS[0].z, aS[0].w,
                        aS[1].x, aS[1].y, aS[1].z, aS[1].w,
                        aS[2].x, aS[2].y, aS[2].z, aS[2].w,
                        aS[3].x, aS[3].y, aS[3].z, aS[3].w};
        if (PRE == 1) {
            #pragma unroll
            for (int j = 0; j < 16; j++) vv[j] = vv[j] / (1.0f + expf(-vv[j]));
        }
        #pragma unroll
        for (int j = 0; j < 8; j++) {
            unsigned hi, lo;
            bf16_split2(vv[2*j], vv[2*j+1], hi, lo);
            Ah[ah2 * 8 + j][ar] = hi;
            Al[ah2 * 8 + j][ar] = lo;
        }
    };
    auto cpB = [&](int c) {
        char* st = smem + (c & 1) * STAGE;
        uint32_t sH = smem_u32(st + 2 * ARR_B) + (uint32_t)(bkp * PADg + bn0) * 4;
        uint32_t sL = smem_u32(st + 3 * ARR_B) + (uint32_t)(bkp * PADg + bn0) * 4;
        const unsigned* gh = bhRow + (size_t)c * 16 * N;
        const unsigned* gl = blRow + (size_t)c * 16 * N;
        cpasync16(sH, gh);       cpasync16(sH + 16, gh + 4);
        cpasync16(sL, gl);       cpasync16(sL + 16, gl + 4);
        CP_COMMIT();
    };

    const int nCh = K >> 5;

    ldgA(0);
    stsA(0);
    cpB(0);
    if (nCh > 1) ldgA(1);
    CP_WAIT0();
    __syncthreads();

    for (int ch = 0; ch < nCh; ch++) {
        if (ch + 1 < nCh) { stsA(ch + 1); cpB(ch + 1); }
        if (ch + 2 < nCh) ldgA(ch + 2);

        // ---- compute on stage ch&1 ----
        char* st = smem + (ch & 1) * STAGE;
        unsigned (*Ahip)[PADg] = (unsigned(*)[PADg])st;
        unsigned (*Alop)[PADg] = (unsigned(*)[PADg])(st + ARR_B);
        unsigned (*Bhip)[PADg] = (unsigned(*)[PADg])(st + 2 * ARR_B);
        unsigned (*Blop)[PADg] = (unsigned(*)[PADg])(st + 3 * ARR_B);

        #pragma unroll
        for (int s = 0; s < 2; s++) {
            const int kb = s * 8;
            unsigned ah[4][4], al[4][4], bh[4][2], bl[4][2];
            #pragma unroll
            for (int mi = 0; mi < 4; mi++) {
                int m0 = warpRow * 64 + mi * 16;
                ah[mi][0] = Ahip[kb + tg    ][m0 + gr];
                ah[mi][1] = Ahip[kb + tg    ][m0 + gr + 8];
                ah[mi][2] = Ahip[kb + tg + 4][m0 + gr];
                ah[mi][3] = Ahip[kb + tg + 4][m0 + gr + 8];
                al[mi][0] = Alop[kb + tg    ][m0 + gr];
                al[mi][1] = Alop[kb + tg    ][m0 + gr + 8];
                al[mi][2] = Alop[kb + tg + 4][m0 + gr];
                al[mi][3] = Alop[kb + tg + 4][m0 + gr + 8];
            }
            #pragma unroll
            for (int ni = 0; ni < 4; ni++) {
                int n0 = warpCol * 32 + ni * 8;
                bh[ni][0] = Bhip[kb + tg    ][n0 + gr];
                bh[ni][1] = Bhip[kb + tg + 4][n0 + gr];
                bl[ni][0] = Blop[kb + tg    ][n0 + gr];
                bl[ni][1] = Blop[kb + tg + 4][n0 + gr];
            }
            #pragma unroll
            for (int mi = 0; mi < 4; mi++)
                #pragma unroll
                for (int ni = 0; ni < 4; ni++)
                    mma16(acc[mi][ni], ah[mi], bh[ni]);
            #pragma unroll
            for (int mi = 0; mi < 4; mi++)
                #pragma unroll
                for (int ni = 0; ni < 4; ni++)
                    mma16(acc[mi][ni], ah[mi], bl[ni]);
            #pragma unroll
            for (int mi = 0; mi < 4; mi++)
                #pragma unroll
                for (int ni = 0; ni < 4; ni++)
                    mma16(acc[mi][ni], al[mi], bh[ni]);
        }

        if (ch + 1 < nCh) {
            CP_WAIT0();
            __syncthreads();
        }
    }

    // ---- epilogue ----
    #pragma unroll
    for (int mi = 0; mi < 4; mi++) {
        #pragma unroll
        for (int half = 0; half < 2; half++) {
            int row = rowBase + warpRow * 64 + mi * 16 + gr + half * 8;
            if (row >= M) continue;
            #pragma unroll
            for (int ni = 0; ni < 4; ni++) {
                int col = colBase + warpCol * 32 + ni * 8 + tg * 2;
                float v0 = acc[mi][ni][half * 2 + 0] + (bias ? bias[col]     : 0.0f);
                float v1 = acc[mi][ni][half * 2 + 1] + (bias ? bias[col + 1] : 0.0f);
                if (EPI == 1) {
                    float t0 = 0.7978845608028654f * (v0 + 0.044715f * v0 * v0 * v0);
                    v0 = 0.5f * v0 * (1.0f + tanhf(t0));
                    float t1 = 0.7978845608028654f * (v1 + 0.044715f * v1 * v1 * v1);
                    v1 = 0.5f * v1 * (1.0f + tanhf(t1));
                } else if (EPI == 2) {
                    float g0 = gate[(size_t)row * gate_stride + col];
                    float g1 = gate[(size_t)row * gate_stride + col + 1];
                    v0 = resid[(size_t)row * N + col]     + g0 * v0;
                    v1 = resid[(size_t)row * N + col + 1] + g1 * v1;
                }
                *(float2*)&C[(size_t)row * N + col] = make_float2(v0, v1);
            }
        }
    }
}

// ---------------- launch ----------------------------------------------------
extern "C" void kernel_launch(void* const* d_in, const int* in_sizes, int n_in,
                              void* d_out, int out_size) {
    const float* x      = (const float*)d_in[0];
    const void*  ei     = d_in[1];
    const float* c      = (const float*)d_in[2];
    const float* w_qkv  = (const float*)d_in[3];
    const float* w_proj = (const float*)d_in[4];
    const float* b_proj = (const float*)d_in[5];
    const float* w_mlp1 = (const float*)d_in[6];
    const float* b_mlp1 = (const float*)d_in[7];
    const float* w_mlp2 = (const float*)d_in[8];
    const float* b_mlp2 = (const float*)d_in[9];
    const float* w_ada  = (const float*)d_in[10];
    const float* b_ada  = (const float*)d_in[11];
    float* out = (float*)d_out;

    float *p_mods, *p_xmod, *p_qkv, *p_agg, *p_x1, *p_h1;
    unsigned *p_whi, *p_wlo;
    cudaGetSymbolAddress((void**)&p_mods, g_mods);
    cudaGetSymbolAddress((void**)&p_xmod, g_xmod);
    cudaGetSymbolAddress((void**)&p_qkv,  g_qkv);
    cudaGetSymbolAddress((void**)&p_agg,  g_agg);
    cudaGetSymbolAddress((void**)&p_x1,   g_x1);
    cudaGetSymbolAddress((void**)&p_h1,   g_h1);
    cudaGetSymbolAddress((void**)&p_whi,  g_whi);
    cudaGetSymbolAddress((void**)&p_wlo,  g_wlo);

    cudaFuncSetAttribute(bgemm128<0,1>, cudaFuncAttributeMaxDynamicSharedMemorySize, SMTOT);
    cudaFuncSetAttribute(bgemm128<0,0>, cudaFuncAttributeMaxDynamicSharedMemorySize, SMTOT);
    cudaFuncSetAttribute(bgemm128<1,0>, cudaFuncAttributeMaxDynamicSharedMemorySize, SMTOT);
    cudaFuncSetAttribute(bgemm128<2,0>, cudaFuncAttributeMaxDynamicSharedMemorySize, SMTOT);

    const int rowsB = (Nn + 127) / 128;   // 391

    // launches 0-4: prologue (edge probe/convert, ada weight split, scratch init)
    k_flag_init<<<1, 1>>>();                                                   // 0
    k_detect <<<(Ee + 255) / 256, 256>>>(ei);                                  // 1
    k_convert<<<(Ee + 255) / 256, 256>>>(ei);                                  // 2
    k_wsplit<<<(64 * MODSc + 255) / 256, 256>>>(w_ada,  HIDc, MODSc,
                                                p_whi + W_ADA_OFF,  p_wlo + W_ADA_OFF);   // 3
    k_init<<<(Nn * HIDc + 255) / 256, 256>>>();                                // 4

    // 5: mods = silu(c) @ w_ada + b_ada    <-- ncu -s 5 profiles THIS
    bgemm128<0,1><<<dim3(MODSc / 128, rowsB), 256, SMTOT>>>(c, p_whi + W_ADA_OFF, p_wlo + W_ADA_OFF,
                                                            b_ada, p_mods, Nn, MODSc, HIDc,
                                                            nullptr, nullptr, 0);
    // 6: xmod = modulate(ln(x), sh_msa, sc_msa)
    k_ln_mod<<<(Nn + 7) / 8, 256>>>(x, p_mods, 0, HIDc, p_xmod);
    // 7: qkv weight split
    k_wsplit<<<(64 * 384 + 255) / 256, 256>>>(w_qkv, HIDc, 384,
                                              p_whi + W_QKV_OFF, p_wlo + W_QKV_OFF);
    // 8: qkv = xmod @ w_qkv
    bgemm128<0,0><<<dim3(384 / 128, rowsB), 256, SMTOT>>>(p_xmod, p_whi + W_QKV_OFF, p_wlo + W_QKV_OFF,
                                                          nullptr, p_qkv, Nn, 384, HIDc,
                                                          nullptr, nullptr, 0);
    // 9: per-edge scores + segment max
    k_edge_score<<<(Ee * 8) / 256, 256>>>(p_qkv);
    // 10: per-edge exp + denominator + message accumulation
    k_edge_msg<<<(Ee * 8) / 256, 256>>>(p_qkv);
    // 11: normalize
    k_norm<<<(Nn * 32 + 255) / 256, 256>>>();
    // 12: proj weight split
    k_wsplit<<<(64 * HIDc + 255) / 256, 256>>>(w_proj, HIDc, HIDc,
                                               p_whi + W_PROJ_OFF, p_wlo + W_PROJ_OFF);
    // 13: x1 = x + g_msa * (agg @ w_proj + b_proj)
    bgemm128<2,0><<<dim3(1, rowsB), 256, SMTOT>>>(p_agg, p_whi + W_PROJ_OFF, p_wlo + W_PROJ_OFF,
                                                  b_proj, p_x1, Nn, HIDc, HIDc,
                                                  x, p_mods + 2 * HIDc, MODSc);
    // 14: xmod = modulate(ln(x1), sh_mlp, sc_mlp)
    k_ln_mod<<<(Nn + 7) / 8, 256>>>(p_x1, p_mods, 3 * HIDc, 4 * HIDc, p_xmod);
    // 15: mlp1 weight split
    k_wsplit<<<(64 * MLPc + 255) / 256, 256>>>(w_mlp1, HIDc, MLPc,
                                               p_whi + W_MLP1_OFF, p_wlo + W_MLP1_OFF);
    // 16: h1 = gelu(xmod @ w_mlp1 + b_mlp1)
    bgemm128<1,0><<<dim3(MLPc / 128, rowsB), 256, SMTOT>>>(p_xmod, p_whi + W_MLP1_OFF, p_wlo + W_MLP1_OFF,
                                                           b_mlp1, p_h1, Nn, MLPc, HIDc,
                                                           nullptr, nullptr, 0);
    // 17: mlp2 weight split
    k_wsplit<<<(256 * HIDc + 255) / 256, 256>>>(w_mlp2, MLPc, HIDc,
                                                p_whi + W_MLP2_OFF, p_wlo + W_MLP2_OFF);
    // 18: out = x1 + g_mlp * (h1 @ w_mlp2 + b_mlp2)
    bgemm128<2,0><<<dim3(1, rowsB), 256, SMTOT>>>(p_h1, p_whi + W_MLP2_OFF, p_wlo + W_MLP2_OFF,
                                                  b_mlp2, out, Nn, HIDc, MLPc,
                                                  p_x1, p_mods + 5 * HIDc, MODSc);
}